// round 17
// baseline (speedup 1.0000x reference)
#include <cuda_runtime.h>
#include <cuda_fp16.h>
#include <math.h>
#include <stdint.h>

#define kT   512
#define kB   64
#define kH   1024
#define kBH  65536
#define kTB  32768
#define kTBH 33554432

// ---------------------------------------------------------------------------
// Scratch (device globals; allocations forbidden)
// ---------------------------------------------------------------------------
struct __align__(16) Scratch {
    float  X[kTBH];                      // X0 = input @ W_ih0^T + biases (fp32)
    __half Ah[kTBH];                     // input as fp16
    __half Whi[4][kH * kH];              // W hi: ih0, hh0, ih1, hh1
    __half Wlo[4][kH * kH];              // W lo (fp16 residual)
    float  bias[2][kH];
    __half hin[2 * kBH];                 // initial h (fp16)
};
__device__ Scratch g_s;

// write-once hidden histories (fp16)
__device__ __half g_h0[kTBH], g_h1[kTBH];

// RED-accumulated pre-activations, 4-deep slots: [slot][b][hidden]
__device__ float g_a0[4][kB][kH];
__device__ float g_a1[4][kB][kH];

// dataflow flags (monotonic counters; fan-in 8; 16 tiles)
__device__ int g_pf0[kT][16], g_pf1[kT][16];
__device__ int g_hf0[kT][16], g_hf1[kT][16];

// ---------------------------------------------------------------------------
// Warp MMA primitives (baseline ISA: fp16 HMMA + ldmatrix)
// ---------------------------------------------------------------------------
__device__ __forceinline__ uint32_t smem_u32(const void* p) {
    uint32_t r;
    asm("{ .reg .u64 t; cvta.to.shared.u64 t, %1; cvt.u32.u64 %0, t; }" : "=r"(r) : "l"(p));
    return r;
}
#define LDSM4(r, addr)                                                        \
    asm volatile("ldmatrix.sync.aligned.m8n8.x4.shared.b16 {%0,%1,%2,%3}, [%4];" \
        : "=r"((r)[0]), "=r"((r)[1]), "=r"((r)[2]), "=r"((r)[3]) : "r"(addr))
#define HMMA(d, a, b)                                                         \
    asm volatile("mma.sync.aligned.m16n8k16.row.col.f32.f16.f16.f32 "         \
        "{%0,%1,%2,%3}, {%4,%5,%6,%7}, {%8,%9}, {%0,%1,%2,%3};"               \
        : "+f"((d)[0]), "+f"((d)[1]), "+f"((d)[2]), "+f"((d)[3])              \
        : "r"((a)[0]), "r"((a)[1]), "r"((a)[2]), "r"((a)[3]),                 \
          "r"((b)[0]), "r"((b)[1]))

#define BARA() asm volatile("bar.sync 1, 256;" ::: "memory")
#define BARB() asm volatile("bar.sync 2, 256;" ::: "memory")

// tight spin: detect latency = one L2 round trip
__device__ __forceinline__ void spin_ge(const int* f, int n) {
    while (true) {
        int v;
        asm volatile("ld.acquire.gpu.global.s32 %0, [%1];" : "=r"(v) : "l"(f));
        if (v >= n) break;
    }
}

// ---------------------------------------------------------------------------
// prep kernels
// ---------------------------------------------------------------------------
__global__ void cvt_half(const float* __restrict__ s, __half* __restrict__ d, int n4) {
    int stride = gridDim.x * blockDim.x;
    for (int i = blockIdx.x * blockDim.x + threadIdx.x; i < n4; i += stride) {
        float4 v = ((const float4*)s)[i];
        __half2* o = (__half2*)d + i * 2;
        o[0] = __floats2half2_rn(v.x, v.y);
        o[1] = __floats2half2_rn(v.z, v.w);
    }
}
// split 4 weight matrices in one launch (each kH*kH/4 = 262144 float4s)
__global__ void split4(const float* w0, const float* w1,
                       const float* w2, const float* w3) {
    const int per = kH * kH / 4;
    int stride = gridDim.x * blockDim.x;
    for (int i = blockIdx.x * blockDim.x + threadIdx.x; i < 4 * per; i += stride) {
        int m = i / per, j = i - m * per;
        const float* s = (m == 0) ? w0 : (m == 1) ? w1 : (m == 2) ? w2 : w3;
        float4 v = ((const float4*)s)[j];
        __half h0 = __float2half(v.x), h1 = __float2half(v.y);
        __half h2 = __float2half(v.z), h3 = __float2half(v.w);
        ((__half2*)g_s.Whi[m])[j * 2 + 0] = __halves2half2(h0, h1);
        ((__half2*)g_s.Whi[m])[j * 2 + 1] = __halves2half2(h2, h3);
        ((__half2*)g_s.Wlo[m])[j * 2 + 0] = __halves2half2(
            __float2half(v.x - __half2float(h0)), __float2half(v.y - __half2float(h1)));
        ((__half2*)g_s.Wlo[m])[j * 2 + 1] = __halves2half2(
            __float2half(v.z - __half2float(h2)), __float2half(v.w - __half2float(h3)));
    }
}
__global__ void bias2(const float* a, const float* b, const float* c,
                      const float* d, float* o0, float* o1) {
    int i = blockIdx.x * 256 + threadIdx.x;
    if (i < kH) { o0[i] = a[i] + b[i]; o1[i] = c[i] + d[i]; }
}
// zero flags + accumulators
__global__ void zero_sync() {
    int i = blockIdx.x * blockDim.x + threadIdx.x;
    if (i < kT * 16) {
        ((int*)g_pf0)[i] = 0; ((int*)g_pf1)[i] = 0;
        ((int*)g_hf0)[i] = 0; ((int*)g_hf1)[i] = 0;
    }
    const int na = 4 * kB * kH;             // 262144 floats per layer
    int stride = gridDim.x * blockDim.x;
    for (int j = i; j < na; j += stride) {
        ((float*)g_a0)[j] = 0.f; ((float*)g_a1)[j] = 0.f;
    }
}

// ---------------------------------------------------------------------------
// Big fp16-x2 GEMM for X0 (proven R14 kernel, unchanged)
// ---------------------------------------------------------------------------
#define GRS 144
#define GBUF (128 * GRS)
#define GEMM_SMEM (3 * GBUF)   // 55296

__global__ void __launch_bounds__(256) gemm_h(
    const __half* __restrict__ Ah, const __half* __restrict__ Whi,
    const __half* __restrict__ Wlo, const float* __restrict__ bias,
    float* __restrict__ C)
{
    extern __shared__ char sm[];
    char* pA  = sm;
    char* pWh = sm + GBUF;
    char* pWl = sm + 2 * GBUF;

    const int tid = threadIdx.x, lane = tid & 31, wid = tid >> 5;
    const int n0 = blockIdx.x * 128, m0 = blockIdx.y * 128;
    const int wm = (wid >> 1) * 32, wn = (wid & 1) * 64;

    const uint32_t aOff = smem_u32(pA) + (wm + (lane & 15)) * GRS + (lane >> 4) * 16;
    const int brow = wn + (lane & 7) + ((lane >> 4) & 1) * 8;
    const uint32_t bOffH = smem_u32(pWh) + brow * GRS + ((lane >> 3) & 1) * 16;
    const uint32_t bOffL = smem_u32(pWl) + brow * GRS + ((lane >> 3) & 1) * 16;

    float acc[2][8][4];
#pragma unroll
    for (int a = 0; a < 2; a++)
#pragma unroll
        for (int b = 0; b < 8; b++)
#pragma unroll
            for (int c = 0; c < 4; c++) acc[a][b][c] = 0.f;

    for (int k0 = 0; k0 < kH; k0 += 64) {
        __syncthreads();
#pragma unroll
        for (int i = 0; i < 4; i++) {
            int q = tid + i * 256;
            int row = q >> 3, c16 = q & 7;
            *(uint4*)(pA  + row * GRS + c16 * 16) =
                *((const uint4*)(Ah  + (size_t)(m0 + row) * kH + k0) + c16);
            *(uint4*)(pWh + row * GRS + c16 * 16) =
                *((const uint4*)(Whi + (size_t)(n0 + row) * kH + k0) + c16);
            *(uint4*)(pWl + row * GRS + c16 * 16) =
                *((const uint4*)(Wlo + (size_t)(n0 + row) * kH + k0) + c16);
        }
        __syncthreads();
#pragma unroll
        for (int kk = 0; kk < 4; kk++) {
            uint32_t ah0[4], ah1[4];
            LDSM4(ah0, aOff + kk * 32);
            LDSM4(ah1, aOff + 16 * GRS + kk * 32);
#pragma unroll
            for (int np = 0; np < 4; np++) {
                uint32_t bh[4], bl[4];
                LDSM4(bh, bOffH + np * 16 * GRS + kk * 32);
                LDSM4(bl, bOffL + np * 16 * GRS + kk * 32);
                HMMA(acc[0][np*2+0], ah0, bh+0); HMMA(acc[0][np*2+1], ah0, bh+2);
                HMMA(acc[1][np*2+0], ah1, bh+0); HMMA(acc[1][np*2+1], ah1, bh+2);
                HMMA(acc[0][np*2+0], ah0, bl+0); HMMA(acc[0][np*2+1], ah0, bl+2);
                HMMA(acc[1][np*2+0], ah1, bl+0); HMMA(acc[1][np*2+1], ah1, bl+2);
            }
        }
    }
    const int g = lane >> 2, tg2 = (lane & 3) * 2;
#pragma unroll
    for (int mf = 0; mf < 2; mf++)
#pragma unroll
        for (int nt = 0; nt < 8; nt++) {
            int m = m0 + wm + mf * 16 + g;
            int n = n0 + wn + nt * 8 + tg2;
            float b0 = bias[n], b1 = bias[n + 1];
            *(float2*)(C + (size_t)m * kH + n) =
                make_float2(acc[mf][nt][0] + b0, acc[mf][nt][1] + b1);
            *(float2*)(C + (size_t)(m + 8) * kH + n) =
                make_float2(acc[mf][nt][2] + b0, acc[mf][nt][3] + b1);
        }
}

// ---------------------------------------------------------------------------
// Warp-specialized fused recurrence, fp16 x2, RED-accumulate exchange (R17).
// 128 CTAs = 16 mt(64 cols) x 8 kc(128 k).
// Producers REDG fragments into g_a{0,1}[slot][b][hid]; owner reads ONE float2.
// ---------------------------------------------------------------------------
#define RS2 272                       // 128 fp16 + 8 pad
#define SLW (64 * RS2)                // 17408: one W slice [64 rows][128 k]
#define OHA  (6 * SLW)
#define OHB0 (7 * SLW)
#define OHB1 (8 * SLW)
#define RNN_SMEM (9 * SLW)            // 156672

__device__ __forceinline__ void stage_h16(char* dst, const __half* __restrict__ src,
                                          int k0, int gtid)
{
#pragma unroll
    for (int i = 0; i < 4; i++) {
        int q = gtid + i * 256;                // 0..1023 (64 rows x 16 uint4)
        int row = q >> 4, c16 = q & 15;
        uint4 v = __ldcg((const uint4*)(src + (size_t)row * kH + k0) + c16);
        *(uint4*)(dst + row * RS2 + c16 * 16) = v;
    }
}
__device__ __forceinline__ void stage_h16x2(char* d0, const __half* __restrict__ s0,
                                            char* d1, const __half* __restrict__ s1,
                                            int k0, int gtid)
{
#pragma unroll
    for (int i = 0; i < 4; i++) {
        int q = gtid + i * 256;
        int row = q >> 4, c16 = q & 15;
        size_t off = (size_t)row * kH + k0;
        uint4 v0 = __ldcg((const uint4*)(s0 + off) + c16);
        uint4 v1 = __ldcg((const uint4*)(s1 + off) + c16);
        *(uint4*)(d0 + row * RS2 + c16 * 16) = v0;
        *(uint4*)(d1 + row * RS2 + c16 * 16) = v1;
    }
}

__global__ void __launch_bounds__(512) rnn_ws(
    float* __restrict__ out_y, float* __restrict__ hfin0,
    float* __restrict__ hfin1)
{
    extern __shared__ char sm[];
    const int tid = threadIdx.x, lane = tid & 31, wid = tid >> 5;
    const int cta = blockIdx.x;
    const int mt = cta >> 3;                  // 0..15 (64 hidden cols)
    const int kc = cta & 7;                   // 0..7 (128-k chunk)
    const int h0c = mt * 64;
    const int k0 = kc * 128;
    const int kt0 = 2 * kc;                   // h-tiles covering our k range
    const int group = wid >> 3;               // 0 = layer0, 1 = layer1
    const int gw = wid & 7;
    const int gtid = tid & 255;

    // ---- cooperative staging of 6 step-invariant W slices [64 rows][128 k] ----
    {
        const __half* wsrc[6] = { g_s.Whi[1], g_s.Wlo[1], g_s.Whi[2],
                                  g_s.Wlo[2], g_s.Whi[3], g_s.Wlo[3] };
#pragma unroll
        for (int sl = 0; sl < 6; sl++) {
            char* dst = sm + sl * SLW;
            const __half* src = wsrc[sl];
#pragma unroll
            for (int i = 0; i < 2; i++) {
                int q = tid + i * 512;
                int row = q >> 4, c16 = q & 15;
                *(uint4*)(dst + row * RS2 + c16 * 16) =
                    *((const uint4*)(src + (size_t)(h0c + row) * kH + k0) + c16);
            }
        }
    }
    __syncthreads();    // LAST full-CTA sync; groups diverge permanently below

    const int bg = gw & 3, cg = gw >> 2;               // 16 b-rows x 32 cols
    const int bb = bg * 16;
    const uint32_t arow = (bb + (lane & 15)) * RS2 + (lane >> 4) * 16;
    const int brow = cg * 32 + (lane & 7) + ((lane >> 4) & 1) * 8;
    const uint32_t bsel = ((lane >> 3) & 1) * 16;

    const uint32_t bW0H = smem_u32(sm + 0 * SLW) + brow * RS2 + bsel;
    const uint32_t bW0L = smem_u32(sm + 1 * SLW) + brow * RS2 + bsel;
    const uint32_t bW1H = smem_u32(sm + 2 * SLW) + brow * RS2 + bsel;
    const uint32_t bW1L = smem_u32(sm + 3 * SLW) + brow * RS2 + bsel;
    const uint32_t bW2H = smem_u32(sm + 4 * SLW) + brow * RS2 + bsel;
    const uint32_t bW2L = smem_u32(sm + 5 * SLW) + brow * RS2 + bsel;

    const int g = lane >> 2, tg2 = (lane & 3) * 2;

    // reduce/publish ownership: 256 threads cover 64 rows x 8 cols (2 each)
    const int rb   = gtid >> 2;                        // batch row 0..63
    const int rcol = kc * 8 + (gtid & 3) * 2;          // col within 64-tile
    const int gcol = h0c + rcol;
    const int gidx = rb * kH + gcol;

    if (group == 0) {
        // ================= GROUP A: layer-0 serial chain =================
        char* pHA = sm + OHA;
        const uint32_t aH = smem_u32(pHA) + arow;

        for (int t = 0; t < kT; t++) {
            if (t >= 1 && gtid < 2) spin_ge(&g_hf0[t - 1][kt0 + gtid], 8);
            if (t >= 4 && gtid == 2) spin_ge(&g_hf0[t - 4][mt], 8);
            BARA();
            stage_h16(pHA, t ? g_h0 + (size_t)(t - 1) * kBH : g_s.hin, k0, gtid);
            float2 xv = __ldcg((const float2*)(g_s.X + (size_t)t * kBH + gidx));
            BARA();

            float acc[4][4];
#pragma unroll
            for (int a = 0; a < 4; a++)
#pragma unroll
                for (int c = 0; c < 4; c++) acc[a][c] = 0.f;
#pragma unroll
            for (int kk = 0; kk < 8; kk++) {
                uint32_t ah[4];
                LDSM4(ah, aH + kk * 32);
#pragma unroll
                for (int np = 0; np < 2; np++) {
                    uint32_t wh[4], wl[4];
                    LDSM4(wh, bW0H + np * 16 * RS2 + kk * 32);
                    LDSM4(wl, bW0L + np * 16 * RS2 + kk * 32);
                    HMMA(acc[np*2+0], ah, wh+0); HMMA(acc[np*2+1], ah, wh+2);
                    HMMA(acc[np*2+0], ah, wl+0); HMMA(acc[np*2+1], ah, wl+2);
                }
            }

            // RED fragments into global accumulator (fire-and-forget)
            {
                float* pa = &g_a0[t & 3][0][0];
                const int b = bb + g;
#pragma unroll
                for (int nt = 0; nt < 4; nt++) {
                    int col = h0c + cg * 32 + nt * 8 + tg2;
                    atomicAdd(pa + b * kH + col,       acc[nt][0]);
                    atomicAdd(pa + b * kH + col + 1,   acc[nt][1]);
                    atomicAdd(pa + (b + 8) * kH + col,     acc[nt][2]);
                    atomicAdd(pa + (b + 8) * kH + col + 1, acc[nt][3]);
                }
            }
            BARA();
            if (gtid == 0) {
                __threadfence(); atomicAdd(&g_pf0[t][mt], 1);
                spin_ge(&g_pf0[t][mt], 8);
            }
            BARA();

            float* pslot = &g_a0[t & 3][0][0] + gidx;
            float2 p = __ldcg((const float2*)pslot);
            float hx = tanhf(xv.x + p.x), hy = tanhf(xv.y + p.y);
            *(__half2*)(g_h0 + (size_t)t * kBH + gidx) = __floats2half2_rn(hx, hy);
            *(float2*)pslot = make_float2(0.f, 0.f);      // re-zero for slot t+4
            if (t == kT - 1) *(float2*)(hfin0 + gidx) = make_float2(hx, hy);
            BARA();
            if (gtid == 0) { __threadfence(); atomicAdd(&g_hf0[t][mt], 1); }
        }
    } else {
        // ================= GROUP B: layer-1 trailing chain =================
        char* pB0 = sm + OHB0;
        char* pB1 = sm + OHB1;
        const uint32_t a0 = smem_u32(pB0) + arow;
        const uint32_t a1 = smem_u32(pB1) + arow;
        const float2 bv = *(const float2*)(g_s.bias[1] + gcol);

        for (int t = 0; t < kT; t++) {
            if (gtid < 2) spin_ge(&g_hf0[t][kt0 + gtid], 8);
            if (t >= 1 && (gtid == 2 || gtid == 3))
                spin_ge(&g_hf1[t - 1][kt0 + (gtid - 2)], 8);
            if (t >= 4 && gtid == 4) spin_ge(&g_hf1[t - 4][mt], 8);
            BARB();
            stage_h16x2(pB0, g_h0 + (size_t)t * kBH,
                        pB1, t ? g_h1 + (size_t)(t - 1) * kBH : g_s.hin + kBH,
                        k0, gtid);
            BARB();

            float acc[4][4];
#pragma unroll
            for (int a = 0; a < 4; a++)
#pragma unroll
                for (int c = 0; c < 4; c++) acc[a][c] = 0.f;
#pragma unroll
            for (int kk = 0; kk < 8; kk++) {
                uint32_t x0[4], x1[4];
                LDSM4(x0, a0 + kk * 32);
                LDSM4(x1, a1 + kk * 32);
#pragma unroll
                for (int np = 0; np < 2; np++) {
                    uint32_t w1h[4], w1l[4], w2h[4], w2l[4];
                    LDSM4(w1h, bW1H + np * 16 * RS2 + kk * 32);
                    LDSM4(w1l, bW1L + np * 16 * RS2 + kk * 32);
                    LDSM4(w2h, bW2H + np * 16 * RS2 + kk * 32);
                    LDSM4(w2l, bW2L + np * 16 * RS2 + kk * 32);
                    HMMA(acc[np*2+0], x0, w1h+0); HMMA(acc[np*2+1], x0, w1h+2);
                    HMMA(acc[np*2+0], x1, w2h+0); HMMA(acc[np*2+1], x1, w2h+2);
                    HMMA(acc[np*2+0], x0, w1l+0); HMMA(acc[np*2+1], x0, w1l+2);
                    HMMA(acc[np*2+0], x1, w2l+0); HMMA(acc[np*2+1], x1, w2l+2);
                }
            }

            {
                float* pa = &g_a1[t & 3][0][0];
                const int b = bb + g;
#pragma unroll
                for (int nt = 0; nt < 4; nt++) {
                    int col = h0c + cg * 32 + nt * 8 + tg2;
                    atomicAdd(pa + b * kH + col,       acc[nt][0]);
                    atomicAdd(pa + b * kH + col + 1,   acc[nt][1]);
                    atomicAdd(pa + (b + 8) * kH + col,     acc[nt][2]);
                    atomicAdd(pa + (b + 8) * kH + col + 1, acc[nt][3]);
                }
            }
            BARB();
            if (gtid == 0) {
                __threadfence(); atomicAdd(&g_pf1[t][mt], 1);
                spin_ge(&g_pf1[t][mt], 8);
            }
            BARB();

            float* pslot = &g_a1[t & 3][0][0] + gidx;
            float2 p = __ldcg((const float2*)pslot);
            float hx = tanhf(bv.x + p.x), hy = tanhf(bv.y + p.y);
            *(float2*)(out_y + (size_t)t * kBH + gidx) = make_float2(hx, hy);
            *(__half2*)(g_h1 + (size_t)t * kBH + gidx) = __floats2half2_rn(hx, hy);
            *(float2*)pslot = make_float2(0.f, 0.f);      // re-zero for slot t+4
            if (t == kT - 1) *(float2*)(hfin1 + gidx) = make_float2(hx, hy);
            BARB();
            if (gtid == 0) { __threadfence(); atomicAdd(&g_hf1[t][mt], 1); }
        }
    }
}

// ---------------------------------------------------------------------------
// Launch
// ---------------------------------------------------------------------------
extern "C" void kernel_launch(void* const* d_in, const int* in_sizes, int n_in,
                              void* d_out, int out_size)
{
    const float* input = (const float*)d_in[0];
    const float* h_0   = (const float*)d_in[1];
    const float* W_ih0 = (const float*)d_in[2];
    const float* b_ih0 = (const float*)d_in[3];
    const float* W_hh0 = (const float*)d_in[4];
    const float* b_hh0 = (const float*)d_in[5];
    const float* W_ih1 = (const float*)d_in[6];
    const float* b_ih1 = (const float*)d_in[7];
    const float* W_hh1 = (const float*)d_in[8];
    const float* b_hh1 = (const float*)d_in[9];
    float* out = (float*)d_out;

    Scratch* s = nullptr;
    cudaGetSymbolAddress((void**)&s, g_s);

    cudaFuncSetAttribute(gemm_h, cudaFuncAttributeMaxDynamicSharedMemorySize, GEMM_SMEM);
    cudaFuncSetAttribute(rnn_ws, cudaFuncAttributeMaxDynamicSharedMemorySize, RNN_SMEM);

    zero_sync<<<128, 256>>>();
    cvt_half<<<2048, 256>>>(input, s->Ah, kTBH / 4);
    split4<<<2048, 256>>>(W_ih0, W_hh0, W_ih1, W_hh1);
    cvt_half<<<128, 256>>>(h_0, s->hin, 2 * kBH / 4);
    bias2<<<4, 256>>>(b_ih0, b_hh0, b_ih1, b_hh1, s->bias[0], s->bias[1]);

    dim3 ggrid(kH / 128, kTB / 128);
    gemm_h<<<ggrid, 256, GEMM_SMEM>>>(s->Ah, s->Whi[0], s->Wlo[0],
                                      s->bias[0], s->X);

    rnn_ws<<<128, 512, RNN_SMEM>>>(out, out + (size_t)kTBH,
                                   out + (size_t)kTBH + kBH);
}